// round 13
// baseline (speedup 1.0000x reference)
#include <cuda_runtime.h>
#include <cuda_bf16.h>
#include <math.h>
#include <stdint.h>

// ---------------------------------------------------------------------------
// Problem constants
// ---------------------------------------------------------------------------
#define HH 64
#define WW 64
#define HWSZ 4096
#define CIN 128
#define TT 4
#define DM 256
#define NQ 300
#define NP 8
#define NLAY 6
#define BATCH 2
#define MROWS (BATCH*HWSZ)      // 8192 spatial rows
#define MQ (BATCH*NQ)           // 600 query rows
#define MS (MQ*NP)              // 4800 sample rows
#define KP1 2304                // 3*3*256

// ---------------------------------------------------------------------------
// Scratch
// ---------------------------------------------------------------------------
constexpr size_t O_WCOMB = 0;                         // 256*512
constexpr size_t O_BCOMB = O_WCOMB + 256*512;         // 256
constexpr size_t O_PY    = O_BCOMB + 256;             // 64*128
constexpr size_t O_PX    = O_PY + 64*128;             // 64*128 (contiguous)
constexpr size_t O_WSMP  = O_PX + 64*128;             // 256*2304
constexpr size_t O_WCAT  = O_WSMP + (size_t)DM*KP1;   // 6*768*256
constexpr size_t O_BCAT  = O_WCAT + (size_t)NLAY*768*256; // 6*768
constexpr size_t O_X     = O_BCAT + NLAY*768;         // 8192*256
constexpr size_t O_LAT   = O_X + (size_t)MROWS*DM;    // 8192*256
constexpr size_t O_F0    = O_LAT + (size_t)MROWS*DM;  // 8192*256
constexpr size_t O_Q     = O_F0 + (size_t)MROWS*DM;   // 600*256
constexpr size_t O_HHQ   = O_Q + MQ*DM;               // 600*768 [hb|h1|qp]
constexpr size_t O_FLAT  = O_HHQ + (size_t)MQ*768;    // 4800*2304
constexpr size_t O_PV    = O_FLAT + (size_t)MS*KP1;   // 4800*256
constexpr size_t O_KV    = O_PV + (size_t)MS*DM;
constexpr size_t O_KVT   = O_KV + MQ*DM;              // 2*256*300
constexpr size_t O_S     = O_KVT + MQ*DM;             // 2*300*300
constexpr size_t O_AO    = O_S + BATCH*NQ*NQ;
constexpr size_t O_HB    = O_AO + MQ*DM;              // final hb 600*256
constexpr size_t O_BOX0  = O_HB + MQ*DM;              // 600*4
constexpr size_t O_BOX1  = O_BOX0 + MQ*4;             // 600*4
constexpr size_t G_TOTAL = O_BOX1 + MQ*4;

__device__ float g_buf[G_TOTAL];

// ---------------------------------------------------------------------------
// BF16 split helpers
// ---------------------------------------------------------------------------
__device__ __forceinline__ void split_bf16(float x, float& hf, float& lf) {
  __nv_bfloat16 h = __float2bfloat16(x);
  hf = __bfloat162float(h);
  lf = x - hf;
}
__device__ __forceinline__ uint32_t pack_bf16(float lo_elem, float hi_elem) {
  __nv_bfloat162 t = __floats2bfloat162_rn(lo_elem, hi_elem);
  return *reinterpret_cast<uint32_t*>(&t);
}
__device__ __forceinline__ void mma_bf16(float* c, const uint32_t* a, const uint32_t* b) {
  asm volatile(
    "mma.sync.aligned.m16n8k16.row.col.f32.bf16.bf16.f32 "
    "{%0,%1,%2,%3},{%4,%5,%6,%7},{%8,%9},{%0,%1,%2,%3};"
    : "+f"(c[0]), "+f"(c[1]), "+f"(c[2]), "+f"(c[3])
    : "r"(a[0]), "r"(a[1]), "r"(a[2]), "r"(a[3]), "r"(b[0]), "r"(b[1]));
}

// ---------------------------------------------------------------------------
// 3xBF16 GEMM (Karatsuba hi/lo). Block 128x64, 8 warps of 32x32, BK=32,
// double-buffered 48KB dynamic smem, fragment-layout + XOR swizzle.
// GATHER: 0 plain A[M,lda]; 1 im2col (tap-hoisted); 2 stem gather;
//         4 mean over 8 point rows; 5 softmax-on-the-fly over raw scores
// EPI: 0=+bias, 1=+bias+relu, 2=+bias+res, 3=+bias+sinepos(aux),
//      5=+bias, relu on gn<512 only, 6=+bias, dual write C and kvT(res)
// ---------------------------------------------------------------------------
template<int EPI, int GATHER>
__global__ __launch_bounds__(256, 2)
void gemm_b16(const float* __restrict__ A, const float* __restrict__ Bw,
              const float* __restrict__ bias, const float* __restrict__ res,
              const float* __restrict__ aux, float* __restrict__ C,
              int M, int N, int K, int lda,
              long long sA, long long sB, long long sC) {
  const int BM = 128, BN = 64, BK = 32;
  extern __shared__ uint32_t smem[];
  uint32_t* SAb = smem;
  uint32_t* SBb = smem + 8192;
  __shared__ float MXs[128], IVs[128];
  __shared__ float scratch2[2][128];

  A  += blockIdx.z * sA;
  Bw += blockIdx.z * sB;
  C  += blockIdx.z * sC;

  int tid = threadIdx.x;
  int bm = blockIdx.y * BM, bn = blockIdx.x * BN;
  int lane = tid & 31, warp = tid >> 5;
  int wm = (warp >> 1) * 32, wn = (warp & 1) * 32;
  int gid = lane >> 2, tig = lane & 3;
  int xr = (lane >> 2) & 7;

  float acc[2][4][4] = {};
  int Kpad = (K + BK - 1) / BK * BK;

  int am4[4], ak4[4], bn2[2], bk2[2];
  #pragma unroll
  for (int l = 0; l < 4; ++l) {
    int li = tid + l * 256;
    am4[l] = li >> 3;
    ak4[l] = (li & 7) * 4;
  }
  #pragma unroll
  for (int l = 0; l < 2; ++l) {
    int li = tid + l * 256;
    bn2[l] = li >> 3;
    bk2[l] = (li & 7) * 4;
  }
  int m2 = tid & 127, khalf = tid >> 7;

  // GATHER==5: per-row softmax statistics pre-pass (rows of raw score A)
  if (GATHER == 5) {
    int r = tid & 127, part = tid >> 7;     // 2 parts x 150 cols
    int gmr = bm + r;
    float mx = -1e30f;
    if (gmr < M) {
      const float* row = A + (size_t)gmr * lda;
      int j0 = part * 150, j1 = j0 + 150;
      for (int j = j0; j < j1 && j < K; ++j) mx = fmaxf(mx, row[j]);
    }
    scratch2[part][r] = mx;
    __syncthreads();
    float m2x = fmaxf(scratch2[0][r], scratch2[1][r]) * 0.0625f;
    __syncthreads();
    float sum = 0.f;
    if (gmr < M) {
      const float* row = A + (size_t)gmr * lda;
      int j0 = part * 150, j1 = j0 + 150;
      for (int j = j0; j < j1 && j < K; ++j) sum += expf(row[j] * 0.0625f - m2x);
    }
    scratch2[part][r] = sum;
    __syncthreads();
    if (tid < 128) {
      MXs[tid] = m2x;
      float tot = scratch2[0][tid] + scratch2[1][tid];
      IVs[tid] = (tot > 0.f) ? 1.f / tot : 0.f;
    }
    __syncthreads();
  }

  // GATHER==1 loop-invariant per-thread geometry
  int Gh[4], Gw[4], Gb[4], Gv[4];
  if (GATHER == 1) {
    #pragma unroll
    for (int l = 0; l < 4; ++l) {
      int gm = bm + am4[l];
      Gv[l] = (gm < M);
      int hw = gm & 4095;
      Gh[l] = hw >> 6; Gw[l] = hw & 63; Gb[l] = (gm >> 12) << 12;
    }
  }

  float4 pa[4], pb[2];
  float pa2[16];

  auto loadA = [&](int k0, int l) -> float4 {
    float4 v = make_float4(0.f, 0.f, 0.f, 0.f);
    int gm = bm + am4[l], gk = k0 + ak4[l];
    if (GATHER == 4) {
      if (gm < M) {
        const float* base = A + ((size_t)gm * 8) * DM + gk;
        float4 s = make_float4(0.f, 0.f, 0.f, 0.f);
        #pragma unroll
        for (int p = 0; p < 8; ++p) {
          float4 t = *reinterpret_cast<const float4*>(base + (size_t)p * DM);
          s.x += t.x; s.y += t.y; s.z += t.z; s.w += t.w;
        }
        v = make_float4(s.x * 0.125f, s.y * 0.125f, s.z * 0.125f, s.w * 0.125f);
      }
    } else if (GATHER == 5) {
      if (gm < M) {
        float mx = MXs[am4[l]], iv = IVs[am4[l]];
        if (gk + 3 < K) {
          float4 r = *reinterpret_cast<const float4*>(A + (size_t)gm * lda + gk);
          v.x = expf(r.x * 0.0625f - mx) * iv;
          v.y = expf(r.y * 0.0625f - mx) * iv;
          v.z = expf(r.z * 0.0625f - mx) * iv;
          v.w = expf(r.w * 0.0625f - mx) * iv;
        } else {
          float t[4] = {0.f, 0.f, 0.f, 0.f};
          #pragma unroll
          for (int e = 0; e < 4; ++e)
            if (gk + e < K)
              t[e] = expf(A[(size_t)gm * lda + gk + e] * 0.0625f - mx) * iv;
          v = make_float4(t[0], t[1], t[2], t[3]);
        }
      }
    } else {
      if (gm < M) {
        if (gk + 3 < K) v = *reinterpret_cast<const float4*>(A + (size_t)gm * lda + gk);
        else {
          float t[4] = {0.f, 0.f, 0.f, 0.f};
          #pragma unroll
          for (int e = 0; e < 4; ++e) if (gk + e < K) t[e] = A[(size_t)gm * lda + gk + e];
          v = make_float4(t[0], t[1], t[2], t[3]);
        }
      }
    }
    return v;
  };
  auto loadB = [&](int k0, int l) -> float4 {
    float4 v = make_float4(0.f, 0.f, 0.f, 0.f);
    int gn = bn + bn2[l], gk = k0 + bk2[l];
    if (gn < N) {
      if (gk + 3 < K) v = *reinterpret_cast<const float4*>(Bw + (size_t)gn * K + gk);
      else {
        float t[4] = {0.f, 0.f, 0.f, 0.f};
        #pragma unroll
        for (int e = 0; e < 4; ++e) if (gk + e < K) t[e] = Bw[(size_t)gn * K + gk + e];
        v = make_float4(t[0], t[1], t[2], t[3]);
      }
    }
    return v;
  };
  auto prefetch = [&](int k0) {
    if (GATHER == 2) {
      int gm = bm + m2;
      int b = gm >> 12, hw = gm & 4095;
      #pragma unroll
      for (int j = 0; j < 16; ++j) {
        int k = k0 + khalf * 16 + j;
        int i = k >> 2, t = k & 3;
        pa2[j] = A[(size_t)(((b << 2) + t) * CIN + i) * HWSZ + hw];
      }
    } else if (GATHER == 1) {
      int tap = k0 >> 8;
      int ky = tap / 3, kx = tap - ky * 3;
      int c0 = k0 & 255;
      #pragma unroll
      for (int l = 0; l < 4; ++l) {
        float4 v = make_float4(0.f, 0.f, 0.f, 0.f);
        int hh = Gh[l] + ky - 1, ww = Gw[l] + kx - 1;
        if (Gv[l] && hh >= 0 && hh < 64 && ww >= 0 && ww < 64)
          v = *reinterpret_cast<const float4*>(
                A + (size_t)(Gb[l] + (hh << 6) + ww) * 256 + c0 + ak4[l]);
        pa[l] = v;
      }
    } else {
      #pragma unroll
      for (int l = 0; l < 4; ++l) pa[l] = loadA(k0, l);
    }
    #pragma unroll
    for (int l = 0; l < 2; ++l) pb[l] = loadB(k0, l);
  };

  auto storeTiles = [&](int buf) {
    uint32_t* SA = SAb + buf * 4096;
    uint32_t* SB = SBb + buf * 2048;
    if (GATHER == 2) {
      int tm = m2 >> 4, rr = m2 & 15;
      #pragma unroll
      for (int j = 0; j < 8; ++j) {
        int lw = (rr & 7) * 4 + (j & 3);
        int reg = (rr >> 3) | ((j >> 2) << 1);
        float h0, l0, h1, l1;
        split_bf16(pa2[2 * j], h0, l0);
        split_bf16(pa2[2 * j + 1], h1, l1);
        int s0 = (((tm * 2 + khalf) * 32 + lw) * 2) ^ ((lw >> 2) & 7);
        SA[s0 * 4 + reg]       = pack_bf16(h0, h1);
        SA[(s0 ^ 1) * 4 + reg] = pack_bf16(l0, l1);
      }
    } else {
      #pragma unroll
      for (int l = 0; l < 4; ++l) {
        float v[4] = {pa[l].x, pa[l].y, pa[l].z, pa[l].w};
        int tm = am4[l] >> 4, rr = am4[l] & 15;
        int tk = ak4[l] >> 4, k16b = ak4[l] & 15;
        #pragma unroll
        for (int e = 0; e < 2; ++e) {
          int k16p = k16b + 2 * e;
          int lw = (rr & 7) * 4 + ((k16p >> 1) & 3);
          int reg = (rr >> 3) | ((k16p >> 3) << 1);
          float h0, l0, h1, l1;
          split_bf16(v[2 * e], h0, l0);
          split_bf16(v[2 * e + 1], h1, l1);
          int s0 = (((tm * 2 + tk) * 32 + lw) * 2) ^ ((lw >> 2) & 7);
          SA[s0 * 4 + reg]       = pack_bf16(h0, h1);
          SA[(s0 ^ 1) * 4 + reg] = pack_bf16(l0, l1);
        }
      }
    }
    #pragma unroll
    for (int l = 0; l < 2; ++l) {
      float v[4] = {pb[l].x, pb[l].y, pb[l].z, pb[l].w};
      int ntile = bn2[l] >> 3, gidn = bn2[l] & 7;
      int np = ntile >> 1, nodd = ntile & 1;
      int tk = bk2[l] >> 4, k16b = bk2[l] & 15;
      #pragma unroll
      for (int e = 0; e < 2; ++e) {
        int k16p = k16b + 2 * e;
        int lw = gidn * 4 + ((k16p >> 1) & 3);
        int reg = k16p >> 3;
        int word = nodd * 2 + reg;
        float h0, l0, h1, l1;
        split_bf16(v[2 * e], h0, l0);
        split_bf16(v[2 * e + 1], h1, l1);
        int s0 = (((np * 2 + tk) * 32 + lw) * 2) ^ ((lw >> 2) & 7);
        SB[s0 * 4 + word]       = pack_bf16(h0, h1);
        SB[(s0 ^ 1) * 4 + word] = pack_bf16(l0, l1);
      }
    }
  };

  prefetch(0);
  storeTiles(0);
  if (BK < Kpad) prefetch(BK);
  __syncthreads();

  int cur = 0;
  for (int k0 = 0; k0 < Kpad; k0 += BK) {
    if (k0 + BK < Kpad) {
      storeTiles(cur ^ 1);
      if (k0 + 2 * BK < Kpad) prefetch(k0 + 2 * BK);
    }
    const uint32_t* SA = SAb + cur * 4096;
    const uint32_t* SB = SBb + cur * 2048;
    #pragma unroll
    for (int tk = 0; tk < 2; ++tk) {
      uint32_t Ahf[2][4], Alf[2][4];
      #pragma unroll
      for (int i = 0; i < 2; ++i) {
        int tm = (wm >> 4) + i;
        int s0 = (((tm * 2 + tk) * 32 + lane) * 2) ^ xr;
        *reinterpret_cast<uint4*>(Ahf[i]) = *reinterpret_cast<const uint4*>(&SA[s0 * 4]);
        *reinterpret_cast<uint4*>(Alf[i]) = *reinterpret_cast<const uint4*>(&SA[(s0 ^ 1) * 4]);
      }
      uint32_t Bhf[2][4], Blf[2][4];
      #pragma unroll
      for (int jp = 0; jp < 2; ++jp) {
        int np = (wn >> 4) + jp;
        int s0 = (((np * 2 + tk) * 32 + lane) * 2) ^ xr;
        *reinterpret_cast<uint4*>(Bhf[jp]) = *reinterpret_cast<const uint4*>(&SB[s0 * 4]);
        *reinterpret_cast<uint4*>(Blf[jp]) = *reinterpret_cast<const uint4*>(&SB[(s0 ^ 1) * 4]);
      }
      #pragma unroll
      for (int i = 0; i < 2; ++i)
        #pragma unroll
        for (int jp = 0; jp < 2; ++jp)
          #pragma unroll
          for (int nodd = 0; nodd < 2; ++nodd) {
            int j = jp * 2 + nodd;
            uint32_t bh[2] = {Bhf[jp][nodd * 2], Bhf[jp][nodd * 2 + 1]};
            uint32_t bl[2] = {Blf[jp][nodd * 2], Blf[jp][nodd * 2 + 1]};
            mma_bf16(acc[i][j], Ahf[i], bh);
            mma_bf16(acc[i][j], Ahf[i], bl);
            mma_bf16(acc[i][j], Alf[i], bh);
          }
    }
    __syncthreads();
    cur ^= 1;
  }

  #pragma unroll
  for (int i = 0; i < 2; ++i) {
    #pragma unroll
    for (int j = 0; j < 4; ++j) {
      int c0 = bn + wn + 8 * j + 2 * tig;
      #pragma unroll
      for (int half = 0; half < 2; ++half) {
        int gm = bm + wm + 16 * i + gid + 8 * half;
        if (gm >= M) continue;
        #pragma unroll
        for (int e = 0; e < 2; ++e) {
          int gn = c0 + e;
          if (gn >= N) continue;
          float v = acc[i][j][half * 2 + e] + (bias ? bias[gn] : 0.f);
          if (EPI == 1) v = fmaxf(v, 0.f);
          if (EPI == 2) v += res[(size_t)gm * N + gn];
          if (EPI == 3) {
            int hw = gm & 4095, h = hw >> 6, w = hw & 63;
            v += (gn < 128) ? aux[h * 128 + gn] : aux[8192 + w * 128 + (gn - 128)];
          }
          if (EPI == 5) { if (gn < 512) v = fmaxf(v, 0.f); }
          if (EPI == 6) {
            int b = (gm >= NQ) ? 1 : 0;
            int kq = gm - b * NQ;
            ((float*)res)[((size_t)(b * DM + gn)) * NQ + kq] = v;
          }
          C[(size_t)gm * N + gn] = v;
        }
      }
    }
  }
}

// ---------------------------------------------------------------------------
// Prologue mega-kernel: sections by blockIdx.x
// ---------------------------------------------------------------------------
#define PRO_GRID 8088
__global__ __launch_bounds__(256)
void k_prologue(const float* __restrict__ w_tf, const float* __restrict__ w_in,
                const float* __restrict__ b_tf, const float* __restrict__ b_in,
                const float* __restrict__ w_sm,
                const float* __restrict__ w_b1, const float* __restrict__ b_b1,
                const float* __restrict__ w_r1, const float* __restrict__ b_r1,
                const float* __restrict__ Wq,  const float* __restrict__ bq,
                const float* __restrict__ q_embed, const float* __restrict__ q_pos,
                const float* __restrict__ boxes0,
                float* __restrict__ wcomb, float* __restrict__ bcomb,
                float* __restrict__ pos,   float* __restrict__ wsmp,
                float* __restrict__ wcat,  float* __restrict__ bcat,
                float* __restrict__ queries, float* __restrict__ boxes) {
  int blk = blockIdx.x, tid = threadIdx.x;
  if (blk < 512) {
    int idx = blk * 256 + tid;
    int dm = idx >> 9, k = idx & 511, i = k >> 2, t = k & 3;
    float s = 0.f;
    for (int c = 0; c < CIN; ++c) {
      const float* wt = w_tf + (c * CIN + i) * 3;
      float we = wt[1];
      if (t != 3) we += wt[0];
      if (t != 0) we += wt[2];
      s += w_in[dm * CIN + c] * we;
    }
    wcomb[idx] = 0.25f * s;
    if (idx < 256) {
      float sb = b_in[idx];
      for (int c = 0; c < CIN; ++c) sb += w_in[idx * CIN + c] * b_tf[c];
      bcomb[idx] = sb;
    }
  } else if (blk < 576) {
    int idx = (blk - 512) * 256 + tid;
    int half = idx >> 13;
    int r = idx & 8191;
    int hw = r >> 7, c = r & 127;
    float dim_t = powf(10000.f, 2.f * (float)(c >> 2) / 64.f);
    float v = (float)(hw + 1) / (64.f + 1e-6f) * 2.f * 3.14159265358979323846f;
    float a = v / dim_t;
    float o = (c & 1) ? cosf(a) : sinf(a);
    pos[half * 8192 + r] = o;
  } else if (blk < 2880) {
    int idx = (blk - 576) * 256 + tid;
    int o = idx / KP1, r = idx - o * KP1;
    int ky = r / 768, rem = r - ky * 768;
    int kx = rem >> 8, c = rem & 255;
    wsmp[idx] = w_sm[(size_t)o * KP1 + c * 9 + ky * 3 + kx];
  } else if (blk < 7488) {
    int r3 = blk - 2880;                    // 0..4607
    int l = r3 / 768, row = r3 - l * 768;
    const float* src;
    float bv;
    if (row < 256)      { src = w_b1 + (size_t)row * 256;                       bv = b_b1[row]; }
    else if (row < 512) { src = w_r1 + (size_t)(row - 256) * 256;               bv = b_r1[row - 256]; }
    else                { src = Wq + (size_t)l * 65536 + (size_t)(row - 512) * 256; bv = bq[l * 256 + row - 512]; }
    wcat[((size_t)l * 768 + row) * 256 + tid] = src[tid];
    if (tid == 0) bcat[l * 768 + row] = bv;
  } else {
    int m = blk - 7488;
    int q = m % NQ;
    queries[m * DM + tid] = q_embed[q * DM + tid] + q_pos[q * DM + tid];
    if (tid < 4) boxes[m * 4 + tid] = boxes0[m * 4 + tid];
  }
}

// ---------------------------------------------------------------------------
// Fused box-update + refpoints + bilinear sampling. grid=(600, 8), block=256.
// Box state is double-buffered: all blocks read box_in; every block computes
// the (identical) updated box locally; only blockIdx.y==0 writes box_out.
// hhq layout per row: [hb(256) | h1(256) | qp(256)], stride 768.
// ---------------------------------------------------------------------------
__global__ __launch_bounds__(256)
void k_refsample(const float* __restrict__ hhq, const float* __restrict__ box_in,
                 float* __restrict__ box_out,
                 const float* __restrict__ w_r2, const float* __restrict__ b_r2,
                 const float* __restrict__ w_b2, const float* __restrict__ b_b2,
                 const float* __restrict__ f0, float* __restrict__ flat,
                 int do_update) {
  int m = blockIdx.x, p = blockIdx.y;
  int tid = threadIdx.x;
  int warp = tid >> 5, lane = tid & 31;
  __shared__ float partial[8];
  __shared__ float dpart[4];
  __shared__ float box_s[4];
  __shared__ float ro_s[2];

  // ro partials: two groups of 128 threads (warps 0-3 -> g=2p, 4-7 -> g=2p+1)
  {
    int g = 2 * p + (warp >> 2);
    int l128 = tid & 127;
    float s = hhq[m * 768 + 256 + l128]       * w_r2[g * DM + l128]
            + hhq[m * 768 + 256 + l128 + 128] * w_r2[g * DM + l128 + 128];
    #pragma unroll
    for (int off = 16; off > 0; off >>= 1) s += __shfl_down_sync(0xffffffffu, s, off);
    if (lane == 0) partial[warp] = s;
  }
  __syncthreads();
  if (warp < 2 && lane == 0) {
    int g = 2 * p + warp;
    float s = partial[warp * 4 + 0] + partial[warp * 4 + 1]
            + partial[warp * 4 + 2] + partial[warp * 4 + 3];
    ro_s[warp] = tanhf(s + b_r2[g]) * 0.5f;
  }
  if (do_update && warp < 4) {
    float s = 0.f;
    for (int d = lane; d < DM; d += 32) s += hhq[m * 768 + d] * w_b2[warp * DM + d];
    #pragma unroll
    for (int off = 16; off > 0; off >>= 1) s += __shfl_down_sync(0xffffffffu, s, off);
    if (lane == 0) dpart[warp] = s;
  }
  __syncthreads();
  if (tid < 4) {
    float nb = box_in[m * 4 + tid];
    if (do_update) {
      float delta = 1.f / (1.f + expf(-(dpart[tid] + b_b2[tid])));
      nb = fminf(fmaxf(nb + 0.1f * tanhf(delta - 0.5f), 0.f), 1.f);
    }
    box_s[tid] = nb;
    if (p == 0) box_out[m * 4 + tid] = nb;
  }
  __syncthreads();

  float rx = fminf(fmaxf(box_s[0] + ro_s[0], 0.f), 1.f);
  float ry = fminf(fmaxf(box_s[1] + ro_s[1], 0.f), 1.f);

  int b = (m >= NQ) ? 1 : 0;
  const float* f = f0 + (size_t)b * HWSZ * DM;
  int c = tid;
  float* outp = flat + ((size_t)m * 8 + p) * KP1;
  #pragma unroll 1
  for (int kk = 0; kk < 9; ++kk) {
    float oy = (float)(kk / 3 - 1), ox = (float)(kk % 3 - 1);
    float x = fminf(fmaxf((rx + ox * (1.f / 64.f)) * 63.f, 0.f), 63.f);
    float y = fminf(fmaxf((ry + oy * (1.f / 64.f)) * 63.f, 0.f), 63.f);
    float x0 = floorf(x), y0 = floorf(y);
    float wx = x - x0, wy = y - y0;
    int x0i = (int)x0, y0i = (int)y0;
    int x1i = min(x0i + 1, 63), y1i = min(y0i + 1, 63);
    float v00 = f[((y0i << 6) + x0i) * DM + c];
    float v01 = f[((y0i << 6) + x1i) * DM + c];
    float v10 = f[((y1i << 6) + x0i) * DM + c];
    float v11 = f[((y1i << 6) + x1i) * DM + c];
    float v = v00 * (1.f - wx) * (1.f - wy) + v01 * wx * (1.f - wy)
            + v10 * (1.f - wx) * wy + v11 * wx * wy;
    outp[kk * 256 + c] = v;
  }
}

// Final: block m: logits + final box update (uses hb from q_final)
__global__ __launch_bounds__(256)
void k_final(const float* __restrict__ queries, const float* __restrict__ w_cls,
             const float* __restrict__ b_cls, const float* __restrict__ hb,
             const float* __restrict__ w_b2, const float* __restrict__ b_b2,
             const float* __restrict__ boxes, float* __restrict__ out) {
  int m = blockIdx.x, t = threadIdx.x;
  __shared__ float red[256];
  red[t] = queries[m * DM + t] * w_cls[t];
  int j = t >> 5, lane = t & 31;
  float s = 0.f;
  if (j < 4) {
    for (int d = lane; d < DM; d += 32) s += hb[m * DM + d] * w_b2[j * DM + d];
    #pragma unroll
    for (int off = 16; off > 0; off >>= 1) s += __shfl_down_sync(0xffffffffu, s, off);
    if (lane == 0) {
      float delta = 1.f / (1.f + expf(-(s + b_b2[j])));
      float nb = boxes[m * 4 + j] + 0.1f * tanhf(delta - 0.5f);
      out[MQ + m * 4 + j] = fminf(fmaxf(nb, 0.f), 1.f);
    }
  }
  __syncthreads();
  for (int st = 128; st > 0; st >>= 1) { if (t < st) red[t] += red[t + st]; __syncthreads(); }
  if (t == 0) out[m] = red[0] + b_cls[0];
}

// ---------------------------------------------------------------------------
static inline dim3 ggrid(int M, int N, int Z = 1) {
  return dim3((N + 63) / 64, (M + 127) / 128, Z);
}
#define GSMEM 49152

extern "C" void kernel_launch(void* const* d_in, const int* in_sizes, int n_in,
                              void* d_out, int out_size) {
  const float* feat   = (const float*)d_in[0];
  const float* boxes0 = (const float*)d_in[1];
  const float* w_tf   = (const float*)d_in[2];
  const float* b_tf   = (const float*)d_in[3];
  const float* w_in   = (const float*)d_in[4];
  const float* b_in   = (const float*)d_in[5];
  const float* w_lat  = (const float*)d_in[6];
  const float* b_lat  = (const float*)d_in[7];
  const float* w_sm   = (const float*)d_in[8];
  const float* b_sm   = (const float*)d_in[9];
  const float* q_embed= (const float*)d_in[10];
  const float* q_pos  = (const float*)d_in[11];
  const float* Wq     = (const float*)d_in[12];
  const float* bq     = (const float*)d_in[13];
  const float* Wo     = (const float*)d_in[14];
  const float* bo     = (const float*)d_in[15];
  const float* Wp1    = (const float*)d_in[16];
  const float* bp1    = (const float*)d_in[17];
  const float* Wp2    = (const float*)d_in[18];
  const float* bp2    = (const float*)d_in[19];
  const float* w_r1   = (const float*)d_in[20];
  const float* b_r1   = (const float*)d_in[21];
  const float* w_r2   = (const float*)d_in[22];
  const float* b_r2   = (const float*)d_in[23];
  const float* w_b1   = (const float*)d_in[24];
  const float* b_b1   = (const float*)d_in[25];
  const float* w_b2   = (const float*)d_in[26];
  const float* b_b2   = (const float*)d_in[27];
  const float* w_cls  = (const float*)d_in[28];
  const float* b_cls  = (const float*)d_in[29];
  float* out = (float*)d_out;

  static bool attr_done = false;
  if (!attr_done) {
    cudaFuncSetAttribute(gemm_b16<0,0>, cudaFuncAttributeMaxDynamicSharedMemorySize, GSMEM);
    cudaFuncSetAttribute(gemm_b16<1,0>, cudaFuncAttributeMaxDynamicSharedMemorySize, GSMEM);
    cudaFuncSetAttribute(gemm_b16<2,0>, cudaFuncAttributeMaxDynamicSharedMemorySize, GSMEM);
    cudaFuncSetAttribute(gemm_b16<0,1>, cudaFuncAttributeMaxDynamicSharedMemorySize, GSMEM);
    cudaFuncSetAttribute(gemm_b16<3,2>, cudaFuncAttributeMaxDynamicSharedMemorySize, GSMEM);
    cudaFuncSetAttribute(gemm_b16<5,0>, cudaFuncAttributeMaxDynamicSharedMemorySize, GSMEM);
    cudaFuncSetAttribute(gemm_b16<6,4>, cudaFuncAttributeMaxDynamicSharedMemorySize, GSMEM);
    cudaFuncSetAttribute(gemm_b16<0,5>, cudaFuncAttributeMaxDynamicSharedMemorySize, GSMEM);
    attr_done = true;
  }

  float* base = nullptr;
  cudaGetSymbolAddress((void**)&base, g_buf);
  float* p_wcomb = base + O_WCOMB;
  float* p_bcomb = base + O_BCOMB;
  float* p_py    = base + O_PY;     // px contiguous at +8192
  float* p_wsmp  = base + O_WSMP;
  float* p_wcat  = base + O_WCAT;
  float* p_bcat  = base + O_BCAT;
  float* p_x     = base + O_X;
  float* p_lat   = base + O_LAT;
  float* p_f0    = base + O_F0;
  float* p_q     = base + O_Q;
  float* p_hhq   = base + O_HHQ;
  float* p_flat  = base + O_FLAT;
  float* p_pv    = base + O_PV;
  float* p_kv    = base + O_KV;
  float* p_kvT   = base + O_KVT;
  float* p_S     = base + O_S;
  float* p_ao    = base + O_AO;
  float* p_hb    = base + O_HB;
  float* p_box0  = base + O_BOX0;
  float* p_box1  = base + O_BOX1;
  float* p_boxbuf[2] = {p_box0, p_box1};

  // ---- single prologue launch ----
  k_prologue<<<PRO_GRID, 256>>>(w_tf, w_in, b_tf, b_in, w_sm,
                                w_b1, b_b1, w_r1, b_r1, Wq, bq,
                                q_embed, q_pos, boxes0,
                                p_wcomb, p_bcomb, p_py, p_wsmp,
                                p_wcat, p_bcat, p_q, p_box0);

  // ---- stem: fused conv3d+mean_T+in-proj GEMM, +pos epi ----
  gemm_b16<3,2><<<ggrid(MROWS, DM), 256, GSMEM>>>(feat, p_wcomb, p_bcomb, nullptr, p_py,
                                                  p_x, MROWS, DM, 512, 512, 0, 0, 0);

  // ---- scale-1 feature ----
  gemm_b16<0,0><<<ggrid(MROWS, DM), 256, GSMEM>>>(p_x, w_lat, b_lat, nullptr, nullptr,
                                                  p_lat, MROWS, DM, DM, DM, 0, 0, 0);
  gemm_b16<0,1><<<ggrid(MROWS, DM), 256, GSMEM>>>(p_lat, p_wsmp, b_sm, nullptr, nullptr,
                                                  p_f0, MROWS, DM, KP1, KP1, 0, 0, 0);

  for (int l = 0; l < NLAY; ++l) {
    const float* Wo_l  = Wo  + (size_t)l * DM * DM;
    const float* bo_l  = bo  + (size_t)l * DM;
    const float* Wp1_l = Wp1 + (size_t)l * DM * KP1;
    const float* bp1_l = bp1 + (size_t)l * DM;
    const float* Wp2_l = Wp2 + (size_t)l * DM * DM;
    const float* bp2_l = bp2 + (size_t)l * DM;

    // merged [hb | h1 | qp] GEMM: N=768, relu on gn<512
    gemm_b16<5,0><<<ggrid(MQ, 768), 256, GSMEM>>>(p_q, p_wcat + (size_t)l * 768 * 256,
                                                  p_bcat + (size_t)l * 768, nullptr, nullptr,
                                                  p_hhq, MQ, 768, DM, DM, 0, 0, 0);

    // fused box-update + refpoints + sampling (parallel over points)
    k_refsample<<<dim3(MQ, NP), 256>>>(p_hhq, p_boxbuf[l & 1], p_boxbuf[(l + 1) & 1],
                                       w_r2, b_r2, w_b2, b_b2,
                                       p_f0, p_flat, l > 0 ? 1 : 0);

    gemm_b16<1,0><<<ggrid(MS, DM), 256, GSMEM>>>(p_flat, Wp1_l, bp1_l, nullptr, nullptr,
                                                 p_pv, MS, DM, KP1, KP1, 0, 0, 0);
    gemm_b16<6,4><<<ggrid(MQ, DM), 256, GSMEM>>>(p_pv, Wp2_l, bp2_l, p_kvT, nullptr,
                                                 p_kv, MQ, DM, DM, DM, 0, 0, 0);

    // attention: raw scores S, then AV with softmax fused into A-loader
    gemm_b16<0,0><<<ggrid(NQ, NQ, BATCH), 256, GSMEM>>>(p_hhq + 512, p_kv, nullptr, nullptr, nullptr,
                                                        p_S, NQ, NQ, DM, 768,
                                                        (long long)NQ * 768, (long long)NQ * DM,
                                                        (long long)NQ * NQ);
    gemm_b16<0,5><<<ggrid(NQ, DM, BATCH), 256, GSMEM>>>(p_S, p_kvT, nullptr, nullptr, nullptr,
                                                        p_ao, NQ, DM, NQ, NQ,
                                                        (long long)NQ * NQ, (long long)DM * NQ,
                                                        (long long)NQ * DM);
    gemm_b16<2,0><<<ggrid(MQ, DM), 256, GSMEM>>>(p_ao, Wo_l, bo_l, p_q, nullptr,
                                                 p_q, MQ, DM, DM, DM, 0, 0, 0);
  }

  // final box-head hb from q_final, then fused logits + final box update
  gemm_b16<1,0><<<ggrid(MQ, DM), 256, GSMEM>>>(p_q, w_b1, b_b1, nullptr, nullptr,
                                               p_hb, MQ, DM, DM, DM, 0, 0, 0);
  k_final<<<MQ, 256>>>(p_q, w_cls, b_cls, p_hb, w_b2, b_b2, p_boxbuf[NLAY & 1], out);
}

// round 15
// speedup vs baseline: 1.0443x; 1.0443x over previous
#include <cuda_runtime.h>
#include <cuda_bf16.h>
#include <math.h>
#include <stdint.h>

// ---------------------------------------------------------------------------
// Problem constants
// ---------------------------------------------------------------------------
#define HH 64
#define WW 64
#define HWSZ 4096
#define CIN 128
#define TT 4
#define DM 256
#define NQ 300
#define NP 8
#define NLAY 6
#define BATCH 2
#define MROWS (BATCH*HWSZ)      // 8192 spatial rows
#define MQ (BATCH*NQ)           // 600 query rows
#define MS (MQ*NP)              // 4800 sample rows
#define KP1 2304                // 3*3*256

// ---------------------------------------------------------------------------
// Scratch
// ---------------------------------------------------------------------------
constexpr size_t O_WCOMB = 0;                         // 256*512
constexpr size_t O_BCOMB = O_WCOMB + 256*512;         // 256
constexpr size_t O_PY    = O_BCOMB + 256;             // 64*128 (px at +8192)
constexpr size_t O_WSMP  = O_PY + 2*64*128;           // 256*2304
constexpr size_t O_WCAT  = O_WSMP + (size_t)DM*KP1;   // 6*768*256
constexpr size_t O_BCAT  = O_WCAT + (size_t)NLAY*768*256; // 6*768
constexpr size_t O_WST2  = O_BCAT + NLAY*768;         // 256*512 folded stem->lat
constexpr size_t O_BST2  = O_WST2 + 256*512;          // 256
constexpr size_t O_PL    = O_BST2 + 256;              // pyl 64*256 | pxl 64*256
constexpr size_t O_LAT   = O_PL + 2*64*256;           // 8192*256
constexpr size_t O_F0    = O_LAT + (size_t)MROWS*DM;  // 8192*256
constexpr size_t O_Q     = O_F0 + (size_t)MROWS*DM;   // 600*256
constexpr size_t O_HHQ   = O_Q + MQ*DM;               // 600*768 [hb|h1|qp]
constexpr size_t O_FLAT  = O_HHQ + (size_t)MQ*768;    // 4800*2304
constexpr size_t O_PV    = O_FLAT + (size_t)MS*KP1;   // 4800*256
constexpr size_t O_KV    = O_PV + (size_t)MS*DM;
constexpr size_t O_KVT   = O_KV + MQ*DM;              // 2*256*300
constexpr size_t O_S     = O_KVT + MQ*DM;             // 2*300*300
constexpr size_t O_AO    = O_S + BATCH*NQ*NQ;
constexpr size_t O_HB    = O_AO + MQ*DM;              // final hb 600*256
constexpr size_t O_BOX   = O_HB + MQ*DM;              // 600*4
constexpr size_t G_TOTAL = O_BOX + MQ*4;

__device__ float g_buf[G_TOTAL];

// ---------------------------------------------------------------------------
// BF16 split helpers
// ---------------------------------------------------------------------------
__device__ __forceinline__ void split_bf16(float x, float& hf, float& lf) {
  __nv_bfloat16 h = __float2bfloat16(x);
  hf = __bfloat162float(h);
  lf = x - hf;
}
__device__ __forceinline__ uint32_t pack_bf16(float lo_elem, float hi_elem) {
  __nv_bfloat162 t = __floats2bfloat162_rn(lo_elem, hi_elem);
  return *reinterpret_cast<uint32_t*>(&t);
}
__device__ __forceinline__ void mma_bf16(float* c, const uint32_t* a, const uint32_t* b) {
  asm volatile(
    "mma.sync.aligned.m16n8k16.row.col.f32.bf16.bf16.f32 "
    "{%0,%1,%2,%3},{%4,%5,%6,%7},{%8,%9},{%0,%1,%2,%3};"
    : "+f"(c[0]), "+f"(c[1]), "+f"(c[2]), "+f"(c[3])
    : "r"(a[0]), "r"(a[1]), "r"(a[2]), "r"(a[3]), "r"(b[0]), "r"(b[1]));
}

// ---------------------------------------------------------------------------
// 3xBF16 GEMM (Karatsuba hi/lo). Block 128x64, 8 warps of 32x32, BK=32,
// double-buffered 48KB dynamic smem, fragment-layout + XOR swizzle.
// GATHER: 0 plain A[M,lda]; 1 im2col (tap-hoisted); 2 stem gather; 4 mean/8
// EPI: 0=+bias, 1=+bias+relu, 2=+bias+res,
//      5=+bias, relu on gn<512 only, 6=+bias, dual write C and kvT(res),
//      7=+bias + pyl[h,gn] + pxl[w,gn] (aux: pyl at 0, pxl at 16384)
// ---------------------------------------------------------------------------
template<int EPI, int GATHER>
__global__ __launch_bounds__(256, 2)
void gemm_b16(const float* __restrict__ A, const float* __restrict__ Bw,
              const float* __restrict__ bias, const float* __restrict__ res,
              const float* __restrict__ aux, float* __restrict__ C,
              int M, int N, int K, int lda,
              long long sA, long long sB, long long sC) {
  const int BM = 128, BN = 64, BK = 32;
  extern __shared__ uint32_t smem[];
  uint32_t* SAb = smem;
  uint32_t* SBb = smem + 8192;

  A  += blockIdx.z * sA;
  Bw += blockIdx.z * sB;
  C  += blockIdx.z * sC;

  int tid = threadIdx.x;
  int bm = blockIdx.y * BM, bn = blockIdx.x * BN;
  int lane = tid & 31, warp = tid >> 5;
  int wm = (warp >> 1) * 32, wn = (warp & 1) * 32;
  int gid = lane >> 2, tig = lane & 3;
  int xr = (lane >> 2) & 7;

  float acc[2][4][4] = {};
  int Kpad = (K + BK - 1) / BK * BK;

  int am4[4], ak4[4], bn2[2], bk2[2];
  #pragma unroll
  for (int l = 0; l < 4; ++l) {
    int li = tid + l * 256;
    am4[l] = li >> 3;
    ak4[l] = (li & 7) * 4;
  }
  #pragma unroll
  for (int l = 0; l < 2; ++l) {
    int li = tid + l * 256;
    bn2[l] = li >> 3;
    bk2[l] = (li & 7) * 4;
  }
  int m2 = tid & 127, khalf = tid >> 7;

  // GATHER==1 loop-invariant per-thread geometry
  int Gh[4], Gw[4], Gb[4], Gv[4];
  if (GATHER == 1) {
    #pragma unroll
    for (int l = 0; l < 4; ++l) {
      int gm = bm + am4[l];
      Gv[l] = (gm < M);
      int hw = gm & 4095;
      Gh[l] = hw >> 6; Gw[l] = hw & 63; Gb[l] = (gm >> 12) << 12;
    }
  }

  float4 pa[4], pb[2];
  float pa2[16];

  auto loadA = [&](int k0, int l) -> float4 {
    float4 v = make_float4(0.f, 0.f, 0.f, 0.f);
    int gm = bm + am4[l], gk = k0 + ak4[l];
    if (GATHER == 4) {
      if (gm < M) {
        const float* base = A + ((size_t)gm * 8) * DM + gk;
        float4 s = make_float4(0.f, 0.f, 0.f, 0.f);
        #pragma unroll
        for (int p = 0; p < 8; ++p) {
          float4 t = *reinterpret_cast<const float4*>(base + (size_t)p * DM);
          s.x += t.x; s.y += t.y; s.z += t.z; s.w += t.w;
        }
        v = make_float4(s.x * 0.125f, s.y * 0.125f, s.z * 0.125f, s.w * 0.125f);
      }
    } else {
      if (gm < M) {
        if (gk + 3 < K) v = *reinterpret_cast<const float4*>(A + (size_t)gm * lda + gk);
        else {
          float t[4] = {0.f, 0.f, 0.f, 0.f};
          #pragma unroll
          for (int e = 0; e < 4; ++e) if (gk + e < K) t[e] = A[(size_t)gm * lda + gk + e];
          v = make_float4(t[0], t[1], t[2], t[3]);
        }
      }
    }
    return v;
  };
  auto loadB = [&](int k0, int l) -> float4 {
    float4 v = make_float4(0.f, 0.f, 0.f, 0.f);
    int gn = bn + bn2[l], gk = k0 + bk2[l];
    if (gn < N) {
      if (gk + 3 < K) v = *reinterpret_cast<const float4*>(Bw + (size_t)gn * K + gk);
      else {
        float t[4] = {0.f, 0.f, 0.f, 0.f};
        #pragma unroll
        for (int e = 0; e < 4; ++e) if (gk + e < K) t[e] = Bw[(size_t)gn * K + gk + e];
        v = make_float4(t[0], t[1], t[2], t[3]);
      }
    }
    return v;
  };
  auto prefetch = [&](int k0) {
    if (GATHER == 2) {
      int gm = bm + m2;
      int b = gm >> 12, hw = gm & 4095;
      #pragma unroll
      for (int j = 0; j < 16; ++j) {
        int k = k0 + khalf * 16 + j;
        int i = k >> 2, t = k & 3;
        pa2[j] = A[(size_t)(((b << 2) + t) * CIN + i) * HWSZ + hw];
      }
    } else if (GATHER == 1) {
      int tap = k0 >> 8;
      int ky = tap / 3, kx = tap - ky * 3;
      int c0 = k0 & 255;
      #pragma unroll
      for (int l = 0; l < 4; ++l) {
        float4 v = make_float4(0.f, 0.f, 0.f, 0.f);
        int hh = Gh[l] + ky - 1, ww = Gw[l] + kx - 1;
        if (Gv[l] && hh >= 0 && hh < 64 && ww >= 0 && ww < 64)
          v = *reinterpret_cast<const float4*>(
                A + (size_t)(Gb[l] + (hh << 6) + ww) * 256 + c0 + ak4[l]);
        pa[l] = v;
      }
    } else {
      #pragma unroll
      for (int l = 0; l < 4; ++l) pa[l] = loadA(k0, l);
    }
    #pragma unroll
    for (int l = 0; l < 2; ++l) pb[l] = loadB(k0, l);
  };

  auto storeTiles = [&](int buf) {
    uint32_t* SA = SAb + buf * 4096;
    uint32_t* SB = SBb + buf * 2048;
    if (GATHER == 2) {
      int tm = m2 >> 4, rr = m2 & 15;
      #pragma unroll
      for (int j = 0; j < 8; ++j) {
        int lw = (rr & 7) * 4 + (j & 3);
        int reg = (rr >> 3) | ((j >> 2) << 1);
        float h0, l0, h1, l1;
        split_bf16(pa2[2 * j], h0, l0);
        split_bf16(pa2[2 * j + 1], h1, l1);
        int s0 = (((tm * 2 + khalf) * 32 + lw) * 2) ^ ((lw >> 2) & 7);
        SA[s0 * 4 + reg]       = pack_bf16(h0, h1);
        SA[(s0 ^ 1) * 4 + reg] = pack_bf16(l0, l1);
      }
    } else {
      #pragma unroll
      for (int l = 0; l < 4; ++l) {
        float v[4] = {pa[l].x, pa[l].y, pa[l].z, pa[l].w};
        int tm = am4[l] >> 4, rr = am4[l] & 15;
        int tk = ak4[l] >> 4, k16b = ak4[l] & 15;
        #pragma unroll
        for (int e = 0; e < 2; ++e) {
          int k16p = k16b + 2 * e;
          int lw = (rr & 7) * 4 + ((k16p >> 1) & 3);
          int reg = (rr >> 3) | ((k16p >> 3) << 1);
          float h0, l0, h1, l1;
          split_bf16(v[2 * e], h0, l0);
          split_bf16(v[2 * e + 1], h1, l1);
          int s0 = (((tm * 2 + tk) * 32 + lw) * 2) ^ ((lw >> 2) & 7);
          SA[s0 * 4 + reg]       = pack_bf16(h0, h1);
          SA[(s0 ^ 1) * 4 + reg] = pack_bf16(l0, l1);
        }
      }
    }
    #pragma unroll
    for (int l = 0; l < 2; ++l) {
      float v[4] = {pb[l].x, pb[l].y, pb[l].z, pb[l].w};
      int ntile = bn2[l] >> 3, gidn = bn2[l] & 7;
      int np = ntile >> 1, nodd = ntile & 1;
      int tk = bk2[l] >> 4, k16b = bk2[l] & 15;
      #pragma unroll
      for (int e = 0; e < 2; ++e) {
        int k16p = k16b + 2 * e;
        int lw = gidn * 4 + ((k16p >> 1) & 3);
        int reg = k16p >> 3;
        int word = nodd * 2 + reg;
        float h0, l0, h1, l1;
        split_bf16(v[2 * e], h0, l0);
        split_bf16(v[2 * e + 1], h1, l1);
        int s0 = (((np * 2 + tk) * 32 + lw) * 2) ^ ((lw >> 2) & 7);
        SB[s0 * 4 + word]       = pack_bf16(h0, h1);
        SB[(s0 ^ 1) * 4 + word] = pack_bf16(l0, l1);
      }
    }
  };

  prefetch(0);
  storeTiles(0);
  if (BK < Kpad) prefetch(BK);
  __syncthreads();

  int cur = 0;
  for (int k0 = 0; k0 < Kpad; k0 += BK) {
    if (k0 + BK < Kpad) {
      storeTiles(cur ^ 1);
      if (k0 + 2 * BK < Kpad) prefetch(k0 + 2 * BK);
    }
    const uint32_t* SA = SAb + cur * 4096;
    const uint32_t* SB = SBb + cur * 2048;
    #pragma unroll
    for (int tk = 0; tk < 2; ++tk) {
      uint32_t Ahf[2][4], Alf[2][4];
      #pragma unroll
      for (int i = 0; i < 2; ++i) {
        int tm = (wm >> 4) + i;
        int s0 = (((tm * 2 + tk) * 32 + lane) * 2) ^ xr;
        *reinterpret_cast<uint4*>(Ahf[i]) = *reinterpret_cast<const uint4*>(&SA[s0 * 4]);
        *reinterpret_cast<uint4*>(Alf[i]) = *reinterpret_cast<const uint4*>(&SA[(s0 ^ 1) * 4]);
      }
      uint32_t Bhf[2][4], Blf[2][4];
      #pragma unroll
      for (int jp = 0; jp < 2; ++jp) {
        int np = (wn >> 4) + jp;
        int s0 = (((np * 2 + tk) * 32 + lane) * 2) ^ xr;
        *reinterpret_cast<uint4*>(Bhf[jp]) = *reinterpret_cast<const uint4*>(&SB[s0 * 4]);
        *reinterpret_cast<uint4*>(Blf[jp]) = *reinterpret_cast<const uint4*>(&SB[(s0 ^ 1) * 4]);
      }
      #pragma unroll
      for (int i = 0; i < 2; ++i)
        #pragma unroll
        for (int jp = 0; jp < 2; ++jp)
          #pragma unroll
          for (int nodd = 0; nodd < 2; ++nodd) {
            int j = jp * 2 + nodd;
            uint32_t bh[2] = {Bhf[jp][nodd * 2], Bhf[jp][nodd * 2 + 1]};
            uint32_t bl[2] = {Blf[jp][nodd * 2], Blf[jp][nodd * 2 + 1]};
            mma_bf16(acc[i][j], Ahf[i], bh);
            mma_bf16(acc[i][j], Ahf[i], bl);
            mma_bf16(acc[i][j], Alf[i], bh);
          }
    }
    __syncthreads();
    cur ^= 1;
  }

  #pragma unroll
  for (int i = 0; i < 2; ++i) {
    #pragma unroll
    for (int j = 0; j < 4; ++j) {
      int c0 = bn + wn + 8 * j + 2 * tig;
      #pragma unroll
      for (int half = 0; half < 2; ++half) {
        int gm = bm + wm + 16 * i + gid + 8 * half;
        if (gm >= M) continue;
        #pragma unroll
        for (int e = 0; e < 2; ++e) {
          int gn = c0 + e;
          if (gn >= N) continue;
          float v = acc[i][j][half * 2 + e] + (bias ? bias[gn] : 0.f);
          if (EPI == 1) v = fmaxf(v, 0.f);
          if (EPI == 2) v += res[(size_t)gm * N + gn];
          if (EPI == 5) { if (gn < 512) v = fmaxf(v, 0.f); }
          if (EPI == 6) {
            int b = (gm >= NQ) ? 1 : 0;
            int kq = gm - b * NQ;
            ((float*)res)[((size_t)(b * DM + gn)) * NQ + kq] = v;
          }
          if (EPI == 7) {
            int hw = gm & 4095, h = hw >> 6, w = hw & 63;
            v += aux[h * 256 + gn] + aux[16384 + w * 256 + gn];
          }
          C[(size_t)gm * N + gn] = v;
        }
      }
    }
  }
}

// ---------------------------------------------------------------------------
// Prologue mega-kernel: sections by blockIdx.x
//  [0,512)       wcomb + bcomb
//  [512,576)     sine pos tables (py | px)
//  [576,2880)    w_sm permute
//  [2880,7488)   wcat: 6 layers x 768 rows [w_b1 ; w_r1 ; Wq_l] + bcat
//  [7488,8088)   qinit + boxes init
// ---------------------------------------------------------------------------
#define PRO_GRID 8088
__global__ __launch_bounds__(256)
void k_prologue(const float* __restrict__ w_tf, const float* __restrict__ w_in,
                const float* __restrict__ b_tf, const float* __restrict__ b_in,
                const float* __restrict__ w_sm,
                const float* __restrict__ w_b1, const float* __restrict__ b_b1,
                const float* __restrict__ w_r1, const float* __restrict__ b_r1,
                const float* __restrict__ Wq,  const float* __restrict__ bq,
                const float* __restrict__ q_embed, const float* __restrict__ q_pos,
                const float* __restrict__ boxes0,
                float* __restrict__ wcomb, float* __restrict__ bcomb,
                float* __restrict__ pos,   float* __restrict__ wsmp,
                float* __restrict__ wcat,  float* __restrict__ bcat,
                float* __restrict__ queries, float* __restrict__ boxes) {
  int blk = blockIdx.x, tid = threadIdx.x;
  if (blk < 512) {
    int idx = blk * 256 + tid;
    int dm = idx >> 9, k = idx & 511, i = k >> 2, t = k & 3;
    float s = 0.f;
    for (int c = 0; c < CIN; ++c) {
      const float* wt = w_tf + (c * CIN + i) * 3;
      float we = wt[1];
      if (t != 3) we += wt[0];
      if (t != 0) we += wt[2];
      s += w_in[dm * CIN + c] * we;
    }
    wcomb[idx] = 0.25f * s;
    if (idx < 256) {
      float sb = b_in[idx];
      for (int c = 0; c < CIN; ++c) sb += w_in[idx * CIN + c] * b_tf[c];
      bcomb[idx] = sb;
    }
  } else if (blk < 576) {
    int idx = (blk - 512) * 256 + tid;
    int half = idx >> 13;
    int r = idx & 8191;
    int hw = r >> 7, c = r & 127;
    float dim_t = powf(10000.f, 2.f * (float)(c >> 2) / 64.f);
    float v = (float)(hw + 1) / (64.f + 1e-6f) * 2.f * 3.14159265358979323846f;
    float a = v / dim_t;
    float o = (c & 1) ? cosf(a) : sinf(a);
    pos[half * 8192 + r] = o;
  } else if (blk < 2880) {
    int idx = (blk - 576) * 256 + tid;
    int o = idx / KP1, r = idx - o * KP1;
    int ky = r / 768, rem = r - ky * 768;
    int kx = rem >> 8, c = rem & 255;
    wsmp[idx] = w_sm[(size_t)o * KP1 + c * 9 + ky * 3 + kx];
  } else if (blk < 7488) {
    int r3 = blk - 2880;                    // 0..4607
    int l = r3 / 768, row = r3 - l * 768;
    const float* src;
    float bv;
    if (row < 256)      { src = w_b1 + (size_t)row * 256;                       bv = b_b1[row]; }
    else if (row < 512) { src = w_r1 + (size_t)(row - 256) * 256;               bv = b_r1[row - 256]; }
    else                { src = Wq + (size_t)l * 65536 + (size_t)(row - 512) * 256; bv = bq[l * 256 + row - 512]; }
    wcat[((size_t)l * 768 + row) * 256 + tid] = src[tid];
    if (tid == 0) bcat[l * 768 + row] = bv;
  } else {
    int m = blk - 7488;
    int q = m % NQ;
    queries[m * DM + tid] = q_embed[q * DM + tid] + q_pos[q * DM + tid];
    if (tid < 4) boxes[m * 4 + tid] = boxes0[m * 4 + tid];
  }
}

// ---------------------------------------------------------------------------
// Prologue-2: fold lat into stem. Sections:
//  [0,512)   Wstem2[o][k] = sum_c w_lat[o][c]*wcomb[c][k]  (+bst2)
//  [512,576) pyl[h][o] = sum_{c<128} py[h][c]*w_lat[o][c]
//  [576,640) pxl[w][o] = sum_{c<128} px[w][c]*w_lat[o][128+c]
// ---------------------------------------------------------------------------
__global__ __launch_bounds__(256)
void k_prologue2(const float* __restrict__ wcomb, const float* __restrict__ bcomb,
                 const float* __restrict__ w_lat, const float* __restrict__ b_lat,
                 const float* __restrict__ pos,
                 float* __restrict__ wst2, float* __restrict__ bst2,
                 float* __restrict__ pl) {
  int blk = blockIdx.x, tid = threadIdx.x;
  if (blk < 512) {
    int idx = blk * 256 + tid;
    int o = idx >> 9, k = idx & 511;
    float s = 0.f;
    for (int c = 0; c < 256; ++c) s += w_lat[o * 256 + c] * wcomb[c * 512 + k];
    wst2[idx] = s;
    if (idx < 256) {
      float sb = b_lat[idx];
      for (int c = 0; c < 256; ++c) sb += w_lat[idx * 256 + c] * bcomb[c];
      bst2[idx] = sb;
    }
  } else if (blk < 576) {
    int idx = (blk - 512) * 256 + tid;      // h(64) x o(256)
    int h = idx >> 8, o = idx & 255;
    float s = 0.f;
    for (int c = 0; c < 128; ++c) s += pos[h * 128 + c] * w_lat[o * 256 + c];
    pl[idx] = s;
  } else {
    int idx = (blk - 576) * 256 + tid;
    int w = idx >> 8, o = idx & 255;
    float s = 0.f;
    for (int c = 0; c < 128; ++c) s += pos[8192 + w * 128 + c] * w_lat[o * 256 + 128 + c];
    pl[16384 + idx] = s;
  }
}

// ---------------------------------------------------------------------------
// Fused box-update + refpoints + bilinear sampling. grid=600, block=256.
// hhq layout per row: [hb(256) | h1(256) | qp(256)], stride 768.
// ---------------------------------------------------------------------------
__global__ __launch_bounds__(256)
void k_refsample(const float* __restrict__ hhq, float* __restrict__ boxes,
                 const float* __restrict__ w_r2, const float* __restrict__ b_r2,
                 const float* __restrict__ w_b2, const float* __restrict__ b_b2,
                 const float* __restrict__ f0, float* __restrict__ flat,
                 int do_update) {
  int m = blockIdx.x;
  int tid = threadIdx.x;
  __shared__ float ro_s[16];
  __shared__ float box_s[4];

  {
    int g = tid >> 4, lane16 = tid & 15;
    float s = 0.f;
    for (int d = lane16; d < DM; d += 16)
      s += hhq[m * 768 + 256 + d] * w_r2[g * DM + d];
    #pragma unroll
    for (int off = 8; off > 0; off >>= 1)
      s += __shfl_down_sync(0xffffffffu, s, off, 16);
    if (lane16 == 0) ro_s[g] = tanhf(s + b_r2[g]) * 0.5f;
  }
  if (do_update) {
    int j = tid >> 5, lane = tid & 31;
    if (j < 4) {
      float s = 0.f;
      for (int d = lane; d < DM; d += 32)
        s += hhq[m * 768 + d] * w_b2[j * DM + d];
      #pragma unroll
      for (int off = 16; off > 0; off >>= 1)
        s += __shfl_down_sync(0xffffffffu, s, off);
      if (lane == 0) {
        float delta = 1.f / (1.f + expf(-(s + b_b2[j])));
        float nb = boxes[m * 4 + j] + 0.1f * tanhf(delta - 0.5f);
        nb = fminf(fmaxf(nb, 0.f), 1.f);
        boxes[m * 4 + j] = nb;
        box_s[j] = nb;
      }
    }
  } else {
    if (tid < 4) box_s[tid] = boxes[m * 4 + tid];
  }
  __syncthreads();

  __shared__ float ref_s[8][2];
  if (tid < 16) {
    int p = tid >> 1, j = tid & 1;
    float v = box_s[j] + ro_s[p * 2 + j];
    ref_s[p][j] = fminf(fmaxf(v, 0.f), 1.f);
  }
  __syncthreads();

  int b = (m >= NQ) ? 1 : 0;
  const float* f = f0 + (size_t)b * HWSZ * DM;
  int c = tid;
  float* outm = flat + (size_t)m * 8 * KP1;
  #pragma unroll 1
  for (int p = 0; p < 8; ++p) {
    float rx = ref_s[p][0], ry = ref_s[p][1];
    float* outp = outm + (size_t)p * KP1;
    #pragma unroll 1
    for (int kk = 0; kk < 9; ++kk) {
      float oy = (float)(kk / 3 - 1), ox = (float)(kk % 3 - 1);
      float x = fminf(fmaxf((rx + ox * (1.f / 64.f)) * 63.f, 0.f), 63.f);
      float y = fminf(fmaxf((ry + oy * (1.f / 64.f)) * 63.f, 0.f), 63.f);
      float x0 = floorf(x), y0 = floorf(y);
      float wx = x - x0, wy = y - y0;
      int x0i = (int)x0, y0i = (int)y0;
      int x1i = min(x0i + 1, 63), y1i = min(y0i + 1, 63);
      float v00 = f[((y0i << 6) + x0i) * DM + c];
      float v01 = f[((y0i << 6) + x1i) * DM + c];
      float v10 = f[((y1i << 6) + x0i) * DM + c];
      float v11 = f[((y1i << 6) + x1i) * DM + c];
      float v = v00 * (1.f - wx) * (1.f - wy) + v01 * wx * (1.f - wy)
              + v10 * (1.f - wx) * wy + v11 * wx * wy;
      outp[kk * 256 + c] = v;
    }
  }
}

__global__ __launch_bounds__(512)
void k_softmax(float* __restrict__ S) {
  int m = blockIdx.x;
  int b = (m >= NQ) ? 1 : 0;
  float* row = S + (size_t)b * NQ * NQ + (size_t)(m - b * NQ) * NQ;
  int t = threadIdx.x;
  __shared__ float red[512];
  float v = (t < NQ) ? row[t] * 0.0625f : -1e30f;
  red[t] = v; __syncthreads();
  for (int s = 256; s > 0; s >>= 1) { if (t < s) red[t] = fmaxf(red[t], red[t + s]); __syncthreads(); }
  float mx = red[0]; __syncthreads();
  float e = (t < NQ) ? expf(v - mx) : 0.f;
  red[t] = e; __syncthreads();
  for (int s = 256; s > 0; s >>= 1) { if (t < s) red[t] += red[t + s]; __syncthreads(); }
  float inv = 1.f / red[0];
  if (t < NQ) row[t] = e * inv;
}

// Final: block m: logits + final box update (uses hb from q_final)
__global__ __launch_bounds__(256)
void k_final(const float* __restrict__ queries, const float* __restrict__ w_cls,
             const float* __restrict__ b_cls, const float* __restrict__ hb,
             const float* __restrict__ w_b2, const float* __restrict__ b_b2,
             const float* __restrict__ boxes, float* __restrict__ out) {
  int m = blockIdx.x, t = threadIdx.x;
  __shared__ float red[256];
  red[t] = queries[m * DM + t] * w_cls[t];
  int j = t >> 5, lane = t & 31;
  float s = 0.f;
  if (j < 4) {
    for (int d = lane; d < DM; d += 32) s += hb[m * DM + d] * w_b2[j * DM + d];
    #pragma unroll
    for (int off = 16; off > 0; off >>= 1) s += __shfl_down_sync(0xffffffffu, s, off);
    if (lane == 0) {
      float delta = 1.f / (1.f + expf(-(s + b_b2[j])));
      float nb = boxes[m * 4 + j] + 0.1f * tanhf(delta - 0.5f);
      out[MQ + m * 4 + j] = fminf(fmaxf(nb, 0.f), 1.f);
    }
  }
  __syncthreads();
  for (int st = 128; st > 0; st >>= 1) { if (t < st) red[t] += red[t + st]; __syncthreads(); }
  if (t == 0) out[m] = red[0] + b_cls[0];
}

// ---------------------------------------------------------------------------
static inline dim3 ggrid(int M, int N, int Z = 1) {
  return dim3((N + 63) / 64, (M + 127) / 128, Z);
}
#define GSMEM 49152

extern "C" void kernel_launch(void* const* d_in, const int* in_sizes, int n_in,
                              void* d_out, int out_size) {
  const float* feat   = (const float*)d_in[0];
  const float* boxes0 = (const float*)d_in[1];
  const float* w_tf   = (const float*)d_in[2];
  const float* b_tf   = (const float*)d_in[3];
  const float* w_in   = (const float*)d_in[4];
  const float* b_in   = (const float*)d_in[5];
  const float* w_lat  = (const float*)d_in[6];
  const float* b_lat  = (const float*)d_in[7];
  const float* w_sm   = (const float*)d_in[8];
  const float* b_sm   = (const float*)d_in[9];
  const float* q_embed= (const float*)d_in[10];
  const float* q_pos  = (const float*)d_in[11];
  const float* Wq     = (const float*)d_in[12];
  const float* bq     = (const float*)d_in[13];
  const float* Wo     = (const float*)d_in[14];
  const float* bo     = (const float*)d_in[15];
  const float* Wp1    = (const float*)d_in[16];
  const float* bp1    = (const float*)d_in[17];
  const float* Wp2    = (const float*)d_in[18];
  const float* bp2    = (const float*)d_in[19];
  const float* w_r1   = (const float*)d_in[20];
  const float* b_r1   = (const float*)d_in[21];
  const float* w_r2   = (const float*)d_in[22];
  const float* b_r2   = (const float*)d_in[23];
  const float* w_b1   = (const float*)d_in[24];
  const float* b_b1   = (const float*)d_in[25];
  const float* w_b2   = (const float*)d_in[26];
  const float* b_b2   = (const float*)d_in[27];
  const float* w_cls  = (const float*)d_in[28];
  const float* b_cls  = (const float*)d_in[29];
  float* out = (float*)d_out;

  static bool attr_done = false;
  if (!attr_done) {
    cudaFuncSetAttribute(gemm_b16<0,0>, cudaFuncAttributeMaxDynamicSharedMemorySize, GSMEM);
    cudaFuncSetAttribute(gemm_b16<1,0>, cudaFuncAttributeMaxDynamicSharedMemorySize, GSMEM);
    cudaFuncSetAttribute(gemm_b16<2,0>, cudaFuncAttributeMaxDynamicSharedMemorySize, GSMEM);
    cudaFuncSetAttribute(gemm_b16<0,1>, cudaFuncAttributeMaxDynamicSharedMemorySize, GSMEM);
    cudaFuncSetAttribute(gemm_b16<7,2>, cudaFuncAttributeMaxDynamicSharedMemorySize, GSMEM);
    cudaFuncSetAttribute(gemm_b16<5,0>, cudaFuncAttributeMaxDynamicSharedMemorySize, GSMEM);
    cudaFuncSetAttribute(gemm_b16<6,4>, cudaFuncAttributeMaxDynamicSharedMemorySize, GSMEM);
    attr_done = true;
  }

  float* base = nullptr;
  cudaGetSymbolAddress((void**)&base, g_buf);
  float* p_wcomb = base + O_WCOMB;
  float* p_bcomb = base + O_BCOMB;
  float* p_py    = base + O_PY;     // px contiguous at +8192
  float* p_wsmp  = base + O_WSMP;
  float* p_wcat  = base + O_WCAT;
  float* p_bcat  = base + O_BCAT;
  float* p_wst2  = base + O_WST2;
  float* p_bst2  = base + O_BST2;
  float* p_pl    = base + O_PL;
  float* p_lat   = base + O_LAT;
  float* p_f0    = base + O_F0;
  float* p_q     = base + O_Q;
  float* p_hhq   = base + O_HHQ;
  float* p_flat  = base + O_FLAT;
  float* p_pv    = base + O_PV;
  float* p_kv    = base + O_KV;
  float* p_kvT   = base + O_KVT;
  float* p_S     = base + O_S;
  float* p_ao    = base + O_AO;
  float* p_hb    = base + O_HB;
  float* p_box   = base + O_BOX;

  // ---- prologue launches ----
  k_prologue<<<PRO_GRID, 256>>>(w_tf, w_in, b_tf, b_in, w_sm,
                                w_b1, b_b1, w_r1, b_r1, Wq, bq,
                                q_embed, q_pos, boxes0,
                                p_wcomb, p_bcomb, p_py, p_wsmp,
                                p_wcat, p_bcat, p_q, p_box);
  k_prologue2<<<640, 256>>>(p_wcomb, p_bcomb, w_lat, b_lat, p_py,
                            p_wst2, p_bst2, p_pl);

  // ---- stem fused all the way to lat (conv3d+mean_T+in-proj+pos+lateral) ----
  gemm_b16<7,2><<<ggrid(MROWS, DM), 256, GSMEM>>>(feat, p_wst2, p_bst2, nullptr, p_pl,
                                                  p_lat, MROWS, DM, 512, 512, 0, 0, 0);
  // ---- smooth 3x3 conv (fused im2col) ----
  gemm_b16<0,1><<<ggrid(MROWS, DM), 256, GSMEM>>>(p_lat, p_wsmp, b_sm, nullptr, nullptr,
                                                  p_f0, MROWS, DM, KP1, KP1, 0, 0, 0);

  for (int l = 0; l < NLAY; ++l) {
    const float* Wo_l  = Wo  + (size_t)l * DM * DM;
    const float* bo_l  = bo  + (size_t)l * DM;
    const float* Wp1_l = Wp1 + (size_t)l * DM * KP1;
    const float* bp1_l = bp1 + (size_t)l * DM;
    const float* Wp2_l = Wp2 + (size_t)l * DM * DM;
    const float* bp2_l = bp2 + (size_t)l * DM;

    // merged [hb | h1 | qp] GEMM: N=768, relu on gn<512
    gemm_b16<5,0><<<ggrid(MQ, 768), 256, GSMEM>>>(p_q, p_wcat + (size_t)l * 768 * 256,
                                                  p_bcat + (size_t)l * 768, nullptr, nullptr,
                                                  p_hhq, MQ, 768, DM, DM, 0, 0, 0);

    // fused box-update + refpoints + sampling
    k_refsample<<<MQ, 256>>>(p_hhq, p_box, w_r2, b_r2, w_b2, b_b2,
                             p_f0, p_flat, l > 0 ? 1 : 0);

    gemm_b16<1,0><<<ggrid(MS, DM), 256, GSMEM>>>(p_flat, Wp1_l, bp1_l, nullptr, nullptr,
                                                 p_pv, MS, DM, KP1, KP1, 0, 0, 0);
    gemm_b16<6,4><<<ggrid(MQ, DM), 256, GSMEM>>>(p_pv, Wp2_l, bp2_l, p_kvT, nullptr,
                                                 p_kv, MQ, DM, DM, DM, 0, 0, 0);

    // attention
    gemm_b16<0,0><<<ggrid(NQ, NQ, BATCH), 256, GSMEM>>>(p_hhq + 512, p_kv, nullptr, nullptr, nullptr,
                                                        p_S, NQ, NQ, DM, 768,
                                                        (long long)NQ * 768, (long long)NQ * DM,
                                                        (long long)NQ * NQ);
    k_softmax<<<MQ, 512>>>(p_S);
    gemm_b16<0,0><<<ggrid(NQ, DM, BATCH), 256, GSMEM>>>(p_S, p_kvT, nullptr, nullptr, nullptr,
                                                        p_ao, NQ, DM, NQ, NQ,
                                                        (long long)NQ * NQ, (long long)DM * NQ,
                                                        (long long)NQ * DM);
    gemm_b16<2,0><<<ggrid(MQ, DM), 256, GSMEM>>>(p_ao, Wo_l, bo_l, p_q, nullptr,
                                                 p_q, MQ, DM, DM, DM, 0, 0, 0);
  }

  // final box-head hb from q_final, then fused logits + final box update
  gemm_b16<1,0><<<ggrid(MQ, DM), 256, GSMEM>>>(p_q, w_b1, b_b1, nullptr, nullptr,
                                               p_hb, MQ, DM, DM, DM, 0, 0, 0);
  k_final<<<MQ, 256>>>(p_q, w_cls, b_cls, p_hb, w_b2, b_b2, p_box, out);
}